// round 1
// baseline (speedup 1.0000x reference)
#include <cuda_runtime.h>
#include <cstdint>
#include <cstddef>

// Problem constants (fixed shapes per reference)
#define N_C   100000      // coarse voxels
#define M_F   400000      // fine voxels
#define K3    27
#define C_IN  32
#define C_H   64
#define C_OUT 32

// ---------------- scratch (static device globals; no runtime alloc) -------
__device__ float g_h1[(size_t)N_C * C_H];          // 25.6 MB ping
__device__ float g_h2[(size_t)N_C * C_H];          // 25.6 MB pong
__device__ float g_xt[(size_t)M_F * C_H];          // 102.4 MB t-conv output (relu'd)
__device__ int   g_cnt[8];                         // per-offset row counts
__device__ int   g_grp[(size_t)8 * M_F];           // per-offset compacted row lists

// ---------------- grouping kernels (t-conv rows by offset k) --------------
__global__ void grp_zero_kernel() {
    if (threadIdx.x < 8) g_cnt[threadIdx.x] = 0;
}

__global__ void grp_build_kernel(const int* __restrict__ off) {
    int m = blockIdx.x * 256 + threadIdx.x;
    if (m < M_F) {
        int k = off[m] & 7;
        int pos = atomicAdd(&g_cnt[k], 1);
        g_grp[(size_t)k * M_F + pos] = m;
    }
}

// ---------------- sparse 3x3x3 conv: out[v] = relu(b + sum_k A(nbr) @ W[k])
// Block = 128 threads, tile = 128 voxels x 64 out-channels.
// Thread (tx=tid&7, ty=tid>>3) owns 8 voxels x 8 channels in registers.
// As stride CIN+1 -> bank (v+ic)%32, conflict-free for the 4 distinct v/warp.
template <int CIN>
__global__ void __launch_bounds__(128, 4)
conv3_kernel(const float* __restrict__ x, const int* __restrict__ nbr,
             const float* __restrict__ W, const float* __restrict__ bias,
             float* __restrict__ out)
{
    constexpr int AST = CIN + 1;
    extern __shared__ float sm[];
    float* As = sm;                 // 128 * AST
    float* Bs = sm + 128 * AST;     // CIN * 64

    const int tid = threadIdx.x;
    const int tx = tid & 7;
    const int ty = tid >> 3;
    const int v0 = blockIdx.x * 128;

    float acc[8][8];
    {
        float br[8];
        #pragma unroll
        for (int c = 0; c < 8; c++) br[c] = __ldg(bias + tx * 8 + c);
        #pragma unroll
        for (int j = 0; j < 8; j++)
            #pragma unroll
            for (int c = 0; c < 8; c++) acc[j][c] = br[c];
    }

    const int gv = v0 + tid;               // gather row owned by this thread
    const bool vvalid = (gv < N_C);

    #pragma unroll 1
    for (int k = 0; k < K3; k++) {
        // stage W[k] -> Bs (contiguous, coalesced float4)
        const float4* Wk = (const float4*)(W + (size_t)k * CIN * 64);
        for (int i = tid; i < CIN * 16; i += 128)
            ((float4*)Bs)[i] = __ldg(Wk + i);

        // gather neighbor feature row (sentinel N_C -> zeros)
        int n = vvalid ? __ldg(nbr + (size_t)gv * K3 + k) : N_C;
        if ((unsigned)n < (unsigned)N_C) {
            const float4* src = (const float4*)(x + (size_t)n * CIN);
            #pragma unroll
            for (int c4 = 0; c4 < CIN / 4; c4++) {
                float4 a = __ldg(src + c4);
                As[tid * AST + c4 * 4 + 0] = a.x;
                As[tid * AST + c4 * 4 + 1] = a.y;
                As[tid * AST + c4 * 4 + 2] = a.z;
                As[tid * AST + c4 * 4 + 3] = a.w;
            }
        } else {
            #pragma unroll
            for (int c = 0; c < CIN; c++) As[tid * AST + c] = 0.f;
        }
        __syncthreads();

        #pragma unroll 8
        for (int ic = 0; ic < CIN; ic++) {
            const float4 b0 = *(const float4*)(Bs + ic * 64 + tx * 8);
            const float4 b1 = *(const float4*)(Bs + ic * 64 + tx * 8 + 4);
            #pragma unroll
            for (int j = 0; j < 8; j++) {
                const float a = As[(ty * 8 + j) * AST + ic];
                acc[j][0] = fmaf(a, b0.x, acc[j][0]);
                acc[j][1] = fmaf(a, b0.y, acc[j][1]);
                acc[j][2] = fmaf(a, b0.z, acc[j][2]);
                acc[j][3] = fmaf(a, b0.w, acc[j][3]);
                acc[j][4] = fmaf(a, b1.x, acc[j][4]);
                acc[j][5] = fmaf(a, b1.y, acc[j][5]);
                acc[j][6] = fmaf(a, b1.z, acc[j][6]);
                acc[j][7] = fmaf(a, b1.w, acc[j][7]);
            }
        }
        __syncthreads();
    }

    #pragma unroll
    for (int j = 0; j < 8; j++) {
        const int ov = v0 + ty * 8 + j;
        if (ov < N_C) {
            float4 o0, o1;
            o0.x = fmaxf(acc[j][0], 0.f); o0.y = fmaxf(acc[j][1], 0.f);
            o0.z = fmaxf(acc[j][2], 0.f); o0.w = fmaxf(acc[j][3], 0.f);
            o1.x = fmaxf(acc[j][4], 0.f); o1.y = fmaxf(acc[j][5], 0.f);
            o1.z = fmaxf(acc[j][6], 0.f); o1.w = fmaxf(acc[j][7], 0.f);
            *(float4*)(out + (size_t)ov * 64 + tx * 8)     = o0;
            *(float4*)(out + (size_t)ov * 64 + tx * 8 + 4) = o1;
        }
    }
}

// ---------------- transposed 2x2x2 conv as 8 grouped gathered GEMMs ------
// blockIdx.y = offset k; rows come from g_grp[k]; A gathered via parent_idx.
// Writes relu(g @ W_t[k] + b_t) scattered into g_xt[m].
__global__ void __launch_bounds__(128, 4)
tconv_kernel(const float* __restrict__ Wt, const float* __restrict__ bt,
             const int* __restrict__ parent)
{
    extern __shared__ float sm[];
    float* As = sm;                    // 128 * 65
    float* Bs = sm + 128 * 65;         // 4096
    int*   s_m = (int*)(Bs + 4096);    // 128

    const int k = blockIdx.y;
    const int cnt = g_cnt[k];
    const int r0 = blockIdx.x * 128;
    if (r0 >= cnt) return;             // uniform per block

    const int tid = threadIdx.x;
    const int tx = tid & 7;
    const int ty = tid >> 3;

    const float4* Wk = (const float4*)(Wt + (size_t)k * 64 * 64);
    for (int i = tid; i < 1024; i += 128)
        ((float4*)Bs)[i] = __ldg(Wk + i);

    // gather: one row per thread
    {
        const int r = r0 + tid;
        int m = -1;
        if (r < cnt) m = g_grp[(size_t)k * M_F + r];
        s_m[tid] = m;
        bool zero = true;
        if (m >= 0) {
            const int p = __ldg(parent + m);
            if ((unsigned)p < (unsigned)N_C) {
                zero = false;
                const float4* src = (const float4*)(g_h1 + (size_t)p * 64);
                #pragma unroll
                for (int c4 = 0; c4 < 16; c4++) {
                    float4 a = __ldg(src + c4);
                    As[tid * 65 + c4 * 4 + 0] = a.x;
                    As[tid * 65 + c4 * 4 + 1] = a.y;
                    As[tid * 65 + c4 * 4 + 2] = a.z;
                    As[tid * 65 + c4 * 4 + 3] = a.w;
                }
            }
        }
        if (zero) {
            #pragma unroll
            for (int c = 0; c < 64; c++) As[tid * 65 + c] = 0.f;
        }
    }
    __syncthreads();

    float acc[8][8];
    {
        float br[8];
        #pragma unroll
        for (int c = 0; c < 8; c++) br[c] = __ldg(bt + tx * 8 + c);
        #pragma unroll
        for (int j = 0; j < 8; j++)
            #pragma unroll
            for (int c = 0; c < 8; c++) acc[j][c] = br[c];
    }

    #pragma unroll 8
    for (int ic = 0; ic < 64; ic++) {
        const float4 b0 = *(const float4*)(Bs + ic * 64 + tx * 8);
        const float4 b1 = *(const float4*)(Bs + ic * 64 + tx * 8 + 4);
        #pragma unroll
        for (int j = 0; j < 8; j++) {
            const float a = As[(ty * 8 + j) * 65 + ic];
            acc[j][0] = fmaf(a, b0.x, acc[j][0]);
            acc[j][1] = fmaf(a, b0.y, acc[j][1]);
            acc[j][2] = fmaf(a, b0.z, acc[j][2]);
            acc[j][3] = fmaf(a, b0.w, acc[j][3]);
            acc[j][4] = fmaf(a, b1.x, acc[j][4]);
            acc[j][5] = fmaf(a, b1.y, acc[j][5]);
            acc[j][6] = fmaf(a, b1.z, acc[j][6]);
            acc[j][7] = fmaf(a, b1.w, acc[j][7]);
        }
    }

    #pragma unroll
    for (int j = 0; j < 8; j++) {
        const int mj = s_m[ty * 8 + j];
        if (mj >= 0) {
            float4 o0, o1;
            o0.x = fmaxf(acc[j][0], 0.f); o0.y = fmaxf(acc[j][1], 0.f);
            o0.z = fmaxf(acc[j][2], 0.f); o0.w = fmaxf(acc[j][3], 0.f);
            o1.x = fmaxf(acc[j][4], 0.f); o1.y = fmaxf(acc[j][5], 0.f);
            o1.z = fmaxf(acc[j][6], 0.f); o1.w = fmaxf(acc[j][7], 0.f);
            *(float4*)(g_xt + (size_t)mj * 64 + tx * 8)     = o0;
            *(float4*)(g_xt + (size_t)mj * 64 + tx * 8 + 4) = o1;
        }
    }
}

// ---------------- decoder: (xt @ Wd1 + bd1) -> relu -> (@ Wd2 + bd2) + xup
__global__ void __launch_bounds__(128, 2)
decoder_kernel(const float* __restrict__ Wd1, const float* __restrict__ bd1,
               const float* __restrict__ Wd2, const float* __restrict__ bd2,
               const float* __restrict__ xup, float* __restrict__ out)
{
    extern __shared__ float sm[];
    float* As = sm;               // 128*65 = 8320
    float* B1 = As + 8320;        // 4096
    float* Cs = B1 + 4096;        // 8320
    float* B2 = Cs + 8320;        // 2048

    const int m0 = blockIdx.x * 128;   // M_F divisible by 128 -> no tail
    const int tid = threadIdx.x;

    // load xt tile (already relu'd), linear rows
    {
        const float4* src = (const float4*)(g_xt + (size_t)(m0 + tid) * 64);
        #pragma unroll
        for (int c4 = 0; c4 < 16; c4++) {
            float4 a = __ldg(src + c4);
            As[tid * 65 + c4 * 4 + 0] = a.x;
            As[tid * 65 + c4 * 4 + 1] = a.y;
            As[tid * 65 + c4 * 4 + 2] = a.z;
            As[tid * 65 + c4 * 4 + 3] = a.w;
        }
    }
    for (int i = tid; i < 1024; i += 128) ((float4*)B1)[i] = __ldg((const float4*)Wd1 + i);
    for (int i = tid; i < 512;  i += 128) ((float4*)B2)[i] = __ldg((const float4*)Wd2 + i);
    __syncthreads();

    // phase 1: [128,64] @ [64,64] + bd1, relu -> Cs
    {
        const int tx = tid & 7;
        const int ty = tid >> 3;
        float acc[8][8];
        float br[8];
        #pragma unroll
        for (int c = 0; c < 8; c++) br[c] = __ldg(bd1 + tx * 8 + c);
        #pragma unroll
        for (int j = 0; j < 8; j++)
            #pragma unroll
            for (int c = 0; c < 8; c++) acc[j][c] = br[c];

        #pragma unroll 8
        for (int ic = 0; ic < 64; ic++) {
            const float4 b0 = *(const float4*)(B1 + ic * 64 + tx * 8);
            const float4 b1v = *(const float4*)(B1 + ic * 64 + tx * 8 + 4);
            #pragma unroll
            for (int j = 0; j < 8; j++) {
                const float a = As[(ty * 8 + j) * 65 + ic];
                acc[j][0] = fmaf(a, b0.x, acc[j][0]);
                acc[j][1] = fmaf(a, b0.y, acc[j][1]);
                acc[j][2] = fmaf(a, b0.z, acc[j][2]);
                acc[j][3] = fmaf(a, b0.w, acc[j][3]);
                acc[j][4] = fmaf(a, b1v.x, acc[j][4]);
                acc[j][5] = fmaf(a, b1v.y, acc[j][5]);
                acc[j][6] = fmaf(a, b1v.z, acc[j][6]);
                acc[j][7] = fmaf(a, b1v.w, acc[j][7]);
            }
        }
        #pragma unroll
        for (int j = 0; j < 8; j++)
            #pragma unroll
            for (int c = 0; c < 8; c++)
                Cs[(ty * 8 + j) * 65 + tx * 8 + c] = fmaxf(acc[j][c], 0.f);
    }
    __syncthreads();

    // phase 2: [128,64] @ [64,32] + bd2 + xup -> out
    {
        const int tx = tid & 3;     // 4 channel-groups of 8
        const int ty = tid >> 2;    // 32 voxel-groups of 4
        float acc[4][8];
        float br[8];
        #pragma unroll
        for (int c = 0; c < 8; c++) br[c] = __ldg(bd2 + tx * 8 + c);
        #pragma unroll
        for (int j = 0; j < 4; j++)
            #pragma unroll
            for (int c = 0; c < 8; c++) acc[j][c] = br[c];

        #pragma unroll 8
        for (int ic = 0; ic < 64; ic++) {
            const float4 b0 = *(const float4*)(B2 + ic * 32 + tx * 8);
            const float4 b1v = *(const float4*)(B2 + ic * 32 + tx * 8 + 4);
            #pragma unroll
            for (int j = 0; j < 4; j++) {
                const float a = Cs[(ty * 4 + j) * 65 + ic];
                acc[j][0] = fmaf(a, b0.x, acc[j][0]);
                acc[j][1] = fmaf(a, b0.y, acc[j][1]);
                acc[j][2] = fmaf(a, b0.z, acc[j][2]);
                acc[j][3] = fmaf(a, b0.w, acc[j][3]);
                acc[j][4] = fmaf(a, b1v.x, acc[j][4]);
                acc[j][5] = fmaf(a, b1v.y, acc[j][5]);
                acc[j][6] = fmaf(a, b1v.z, acc[j][6]);
                acc[j][7] = fmaf(a, b1v.w, acc[j][7]);
            }
        }

        #pragma unroll
        for (int j = 0; j < 4; j++) {
            const int m = m0 + ty * 4 + j;
            const float4 u0 = __ldg((const float4*)(xup + (size_t)m * 32 + tx * 8));
            const float4 u1 = __ldg((const float4*)(xup + (size_t)m * 32 + tx * 8 + 4));
            float4 o0, o1;
            o0.x = acc[j][0] + u0.x; o0.y = acc[j][1] + u0.y;
            o0.z = acc[j][2] + u0.z; o0.w = acc[j][3] + u0.w;
            o1.x = acc[j][4] + u1.x; o1.y = acc[j][5] + u1.y;
            o1.z = acc[j][6] + u1.z; o1.w = acc[j][7] + u1.w;
            *(float4*)(out + (size_t)m * 32 + tx * 8)     = o0;
            *(float4*)(out + (size_t)m * 32 + tx * 8 + 4) = o1;
        }
    }
}

// ---------------- launch -------------------------------------------------
extern "C" void kernel_launch(void* const* d_in, const int* in_sizes, int n_in,
                              void* d_out, int out_size)
{
    const float* feats  = (const float*)d_in[0];
    const float* xup    = (const float*)d_in[1];
    const int*   nbr    = (const int*)  d_in[2];
    const int*   parent = (const int*)  d_in[3];
    const int*   off    = (const int*)  d_in[4];
    const float* W1  = (const float*)d_in[5];
    const float* b1  = (const float*)d_in[6];
    const float* W2  = (const float*)d_in[7];
    const float* b2  = (const float*)d_in[8];
    const float* W3  = (const float*)d_in[9];
    const float* b3  = (const float*)d_in[10];
    const float* Wt  = (const float*)d_in[11];
    const float* bt  = (const float*)d_in[12];
    const float* Wd1 = (const float*)d_in[13];
    const float* bd1 = (const float*)d_in[14];
    const float* Wd2 = (const float*)d_in[15];
    const float* bd2 = (const float*)d_in[16];
    float* out = (float*)d_out;

    float *h1, *h2;
    cudaGetSymbolAddress((void**)&h1, g_h1);
    cudaGetSymbolAddress((void**)&h2, g_h2);

    const int SMEM32 = (128 * 33 + 32 * 64) * 4;               // 25088
    const int SMEM64 = (128 * 65 + 64 * 64) * 4;               // 49664
    const int SMEMT  = SMEM64 + 128 * 4;                       // 50176
    const int SMEMD  = (8320 + 4096 + 8320 + 2048) * 4;        // 91136

    cudaFuncSetAttribute(conv3_kernel<32>, cudaFuncAttributeMaxDynamicSharedMemorySize, SMEM32);
    cudaFuncSetAttribute(conv3_kernel<64>, cudaFuncAttributeMaxDynamicSharedMemorySize, SMEM64);
    cudaFuncSetAttribute(tconv_kernel,     cudaFuncAttributeMaxDynamicSharedMemorySize, SMEMT);
    cudaFuncSetAttribute(decoder_kernel,   cudaFuncAttributeMaxDynamicSharedMemorySize, SMEMD);

    const int conv_grid = (N_C + 127) / 128;   // 782
    const int m_tiles   = M_F / 128;           // 3125 (exact)

    grp_zero_kernel<<<1, 32>>>();
    grp_build_kernel<<<(M_F + 255) / 256, 256>>>(off);

    conv3_kernel<32><<<conv_grid, 128, SMEM32>>>(feats, nbr, W1, b1, h1);
    conv3_kernel<64><<<conv_grid, 128, SMEM64>>>(h1,    nbr, W2, b2, h2);
    conv3_kernel<64><<<conv_grid, 128, SMEM64>>>(h2,    nbr, W3, b3, h1);

    tconv_kernel<<<dim3(m_tiles, 8), 128, SMEMT>>>(Wt, bt, parent);

    decoder_kernel<<<m_tiles, 128, SMEMD>>>(Wd1, bd1, Wd2, bd2, xup, out);
}

// round 3
// speedup vs baseline: 2.9697x; 2.9697x over previous
#include <cuda_runtime.h>
#include <cstdint>
#include <cstddef>

#define N_C   100000
#define M_F   400000

// ---------------- scratch (static device globals; no runtime alloc) -------
__device__ float g_h1[(size_t)N_C * 64];
__device__ float g_h2[(size_t)N_C * 64];
__device__ float g_xt[(size_t)M_F * 64];
__device__ int   g_cnt[8];
__device__ int   g_grp[(size_t)8 * M_F];
// fragment-shuffled tf32 weights
__device__ float g_Bs1[27 * 32 * 64];
__device__ float g_Bs2[27 * 64 * 64];
__device__ float g_Bs3[27 * 64 * 64];
__device__ float g_Bt [ 8 * 64 * 64];
__device__ float g_Bd1[64 * 64];
__device__ float g_Bd2[64 * 32];

// ---------------- small helpers ------------------------------------------
__device__ __forceinline__ uint32_t f2tf(float f) {
    uint32_t u;
    asm("cvt.rna.tf32.f32 %0, %1;" : "=r"(u) : "f"(f));
    return u;
}
__device__ __forceinline__ void cp16(uint32_t dst, const void* src, int bytes) {
    asm volatile("cp.async.cg.shared.global [%0], [%1], 16, %2;"
                 :: "r"(dst), "l"(src), "r"(bytes));
}
__device__ __forceinline__ void cp_commit() {
    asm volatile("cp.async.commit_group;");
}
__device__ __forceinline__ void mma_tf32(float* c, const uint32_t* a, const uint32_t* b) {
    asm volatile("mma.sync.aligned.m16n8k8.row.col.f32.tf32.tf32.f32 "
                 "{%0,%1,%2,%3}, {%4,%5,%6,%7}, {%8,%9}, {%0,%1,%2,%3};"
                 : "+f"(c[0]), "+f"(c[1]), "+f"(c[2]), "+f"(c[3])
                 : "r"(a[0]), "r"(a[1]), "r"(a[2]), "r"(a[3]),
                   "r"(b[0]), "r"(b[1]));
}

// ---------------- grouping kernels ---------------------------------------
__global__ void grp_zero_kernel() {
    if (threadIdx.x < 8) g_cnt[threadIdx.x] = 0;
}
__global__ void grp_build_kernel(const int* __restrict__ off) {
    int m = blockIdx.x * 256 + threadIdx.x;
    if (m < M_F) {
        int k = off[m] & 7;
        int pos = atomicAdd(&g_cnt[k], 1);
        g_grp[(size_t)k * M_F + pos] = m;
    }
}

// ---------------- weight shuffle: [K][CIN][COUT] -> frag order -----------
// out idx = ((k*KS + ks)*NF + nf)*64 + lane*2 + reg
// where ic = ks*8 + reg*4 + (lane&3), oc = nf*8 + (lane>>2)
__global__ void prep_shuffle(const float* __restrict__ W, float* __restrict__ out,
                             int total, int CIN, int COUT) {
    int idx = blockIdx.x * 256 + threadIdx.x;
    if (idx >= total) return;
    int reg  = idx & 1;
    int lane = (idx >> 1) & 31;
    int nfq  = idx >> 6;
    int NF   = COUT >> 3;
    int nf   = nfq % NF;
    int kks  = nfq / NF;
    int KSn  = CIN >> 3;
    int ks   = kks % KSn;
    int k    = kks / KSn;
    int ic   = ks * 8 + reg * 4 + (lane & 3);
    int oc   = nf * 8 + (lane >> 2);
    out[idx] = __uint_as_float(f2tf(__ldg(W + ((size_t)k * CIN + ic) * COUT + oc)));
}

// ---------------- sparse 3x3x3 conv via mma.sync tf32 --------------------
// Block 128 thr / 4 warps; tile 128 voxels x 64 out-ch; warp = 32 rows x 64 cols.
template<int CIN>
__global__ void __launch_bounds__(128)
conv3_mma(const float* __restrict__ x, const int* __restrict__ nbr,
          const float* __restrict__ Bw, const float* __restrict__ bias,
          float* __restrict__ out)
{
    constexpr int SAp  = CIN + 4;
    constexpr int KS   = CIN / 8;
    constexpr int ABUF = 128 * SAp;
    constexpr int BBUF = CIN * 64;
    extern __shared__ float sm[];
    float* As = sm;                 // 2 * ABUF
    float* Bs = sm + 2 * ABUF;      // 2 * BBUF
    const uint32_t As_u = (uint32_t)__cvta_generic_to_shared(As);
    const uint32_t Bs_u = (uint32_t)__cvta_generic_to_shared(Bs);

    const int tid  = threadIdx.x;
    const int lane = tid & 31;
    const int w    = tid >> 5;
    const int v0   = blockIdx.x * 128;
    const int r    = lane >> 2;
    const int cq   = lane & 3;

    float acc[2][8][4];
    #pragma unroll
    for (int nf = 0; nf < 8; nf++) {
        float blo = __ldg(bias + nf * 8 + cq * 2);
        float bhi = __ldg(bias + nf * 8 + cq * 2 + 1);
        #pragma unroll
        for (int mf = 0; mf < 2; mf++) {
            acc[mf][nf][0] = blo; acc[mf][nf][1] = bhi;
            acc[mf][nf][2] = blo; acc[mf][nf][3] = bhi;
        }
    }

    const int  gv  = v0 + tid;
    const bool vok = gv < N_C;

    auto stage = [&](int k, int buf) {
        int n = vok ? __ldg(nbr + (size_t)gv * 27 + k) : N_C;
        int bytes = (n < N_C) ? 16 : 0;
        const float* src = x + (size_t)(n < N_C ? n : 0) * CIN;
        uint32_t dst = As_u + (uint32_t)(buf * ABUF + tid * SAp) * 4u;
        #pragma unroll
        for (int c4 = 0; c4 < CIN / 4; c4++)
            cp16(dst + c4 * 16, src + c4 * 4, bytes);
        const float* bsrc = Bw + (size_t)k * BBUF + tid * 4;
        uint32_t bdst = Bs_u + (uint32_t)(buf * BBUF + tid * 4) * 4u;
        #pragma unroll
        for (int i = 0; i < BBUF / 512; i++)
            cp16(bdst + i * 2048, bsrc + i * 512, 16);
    };

    stage(0, 0);
    cp_commit();
    int cbuf = 0;
    #pragma unroll 1
    for (int k = 0; k < 27; k++) {
        if (k < 26) {
            stage(k + 1, cbuf ^ 1);
            cp_commit();
            asm volatile("cp.async.wait_group 1;");
        } else {
            asm volatile("cp.async.wait_group 0;");
        }
        __syncthreads();

        const float* Ab = As + cbuf * ABUF + w * 32 * SAp;
        const float* Bb = Bs + cbuf * BBUF;
        #pragma unroll
        for (int ks = 0; ks < KS; ks++) {
            uint32_t a[2][4];
            #pragma unroll
            for (int mf = 0; mf < 2; mf++) {
                const float* ap = Ab + (mf * 16 + r) * SAp + ks * 8 + cq;
                a[mf][0] = f2tf(ap[0]);
                a[mf][1] = f2tf(ap[8 * SAp]);
                a[mf][2] = f2tf(ap[4]);
                a[mf][3] = f2tf(ap[8 * SAp + 4]);
            }
            #pragma unroll
            for (int nf = 0; nf < 8; nf++) {
                uint2 bv = *(const uint2*)(Bb + (ks * 8 + nf) * 64 + lane * 2);
                uint32_t b[2] = {bv.x, bv.y};
                mma_tf32(acc[0][nf], a[0], b);
                mma_tf32(acc[1][nf], a[1], b);
            }
        }
        __syncthreads();
        cbuf ^= 1;
    }

    #pragma unroll
    for (int mf = 0; mf < 2; mf++) {
        int row = v0 + w * 32 + mf * 16 + r;
        if (row < N_C) {
            float* op = out + (size_t)row * 64 + cq * 2;
            #pragma unroll
            for (int nf = 0; nf < 8; nf++) {
                float2 v = make_float2(fmaxf(acc[mf][nf][0], 0.f),
                                       fmaxf(acc[mf][nf][1], 0.f));
                *(float2*)(op + nf * 8) = v;
            }
        }
        if (row + 8 < N_C) {
            float* op = out + (size_t)(row + 8) * 64 + cq * 2;
            #pragma unroll
            for (int nf = 0; nf < 8; nf++) {
                float2 v = make_float2(fmaxf(acc[mf][nf][2], 0.f),
                                       fmaxf(acc[mf][nf][3], 0.f));
                *(float2*)(op + nf * 8) = v;
            }
        }
    }
}

// ---------------- transposed conv (grouped) via mma ----------------------
__global__ void __launch_bounds__(128)
tconv_mma(const float* __restrict__ bt, const int* __restrict__ parent)
{
    extern __shared__ float sm[];
    float* As = sm;                   // 128*68
    float* Bs = sm + 128 * 68;        // 4096
    int*   s_m = (int*)(Bs + 4096);   // 128
    const uint32_t As_u = (uint32_t)__cvta_generic_to_shared(As);
    const uint32_t Bs_u = (uint32_t)__cvta_generic_to_shared(Bs);

    const int k   = blockIdx.y;
    const int cnt = g_cnt[k];
    const int r0  = blockIdx.x * 128;
    if (r0 >= cnt) return;

    const int tid = threadIdx.x, lane = tid & 31, w = tid >> 5;
    const int r = lane >> 2, cq = lane & 3;

    {
        int rr = r0 + tid;
        int m = (rr < cnt) ? g_grp[(size_t)k * M_F + rr] : -1;
        s_m[tid] = m;
        int p = (m >= 0) ? __ldg(parent + m) : N_C;
        int bytes = (p < N_C) ? 16 : 0;
        const float* src = g_h1 + (size_t)(p < N_C ? p : 0) * 64;
        uint32_t dst = As_u + (uint32_t)(tid * 68) * 4u;
        #pragma unroll
        for (int c4 = 0; c4 < 16; c4++) cp16(dst + c4 * 16, src + c4 * 4, bytes);
        const float* bsrc = g_Bt + (size_t)k * 4096 + tid * 4;
        uint32_t bdst = Bs_u + (uint32_t)(tid * 4) * 4u;
        #pragma unroll
        for (int i = 0; i < 8; i++) cp16(bdst + i * 2048, bsrc + i * 512, 16);
    }
    cp_commit();
    asm volatile("cp.async.wait_group 0;");
    __syncthreads();

    float acc[2][8][4];
    #pragma unroll
    for (int nf = 0; nf < 8; nf++) {
        float blo = __ldg(bt + nf * 8 + cq * 2);
        float bhi = __ldg(bt + nf * 8 + cq * 2 + 1);
        #pragma unroll
        for (int mf = 0; mf < 2; mf++) {
            acc[mf][nf][0] = blo; acc[mf][nf][1] = bhi;
            acc[mf][nf][2] = blo; acc[mf][nf][3] = bhi;
        }
    }

    const float* Ab = As + w * 32 * 68;
    #pragma unroll
    for (int ks = 0; ks < 8; ks++) {
        uint32_t a[2][4];
        #pragma unroll
        for (int mf = 0; mf < 2; mf++) {
            const float* ap = Ab + (mf * 16 + r) * 68 + ks * 8 + cq;
            a[mf][0] = f2tf(ap[0]);
            a[mf][1] = f2tf(ap[8 * 68]);
            a[mf][2] = f2tf(ap[4]);
            a[mf][3] = f2tf(ap[8 * 68 + 4]);
        }
        #pragma unroll
        for (int nf = 0; nf < 8; nf++) {
            uint2 bv = *(const uint2*)(Bs + (ks * 8 + nf) * 64 + lane * 2);
            uint32_t b[2] = {bv.x, bv.y};
            mma_tf32(acc[0][nf], a[0], b);
            mma_tf32(acc[1][nf], a[1], b);
        }
    }

    #pragma unroll
    for (int mf = 0; mf < 2; mf++) {
        int rl = w * 32 + mf * 16 + r;
        int m = s_m[rl];
        if (m >= 0) {
            float* op = g_xt + (size_t)m * 64 + cq * 2;
            #pragma unroll
            for (int nf = 0; nf < 8; nf++) {
                float2 v = make_float2(fmaxf(acc[mf][nf][0], 0.f),
                                       fmaxf(acc[mf][nf][1], 0.f));
                *(float2*)(op + nf * 8) = v;
            }
        }
        int m2 = s_m[rl + 8];
        if (m2 >= 0) {
            float* op = g_xt + (size_t)m2 * 64 + cq * 2;
            #pragma unroll
            for (int nf = 0; nf < 8; nf++) {
                float2 v = make_float2(fmaxf(acc[mf][nf][2], 0.f),
                                       fmaxf(acc[mf][nf][3], 0.f));
                *(float2*)(op + nf * 8) = v;
            }
        }
    }
}

// ---------------- decoder: 64->64 relu -> 64->32 + residual --------------
__global__ void __launch_bounds__(128)
decoder_mma(const float* __restrict__ bd1, const float* __restrict__ bd2,
            const float* __restrict__ xup, float* __restrict__ out)
{
    extern __shared__ float sm[];
    float* As = sm;                 // 8704
    float* Cs = sm + 8704;          // 8704
    float* B1 = sm + 17408;         // 4096
    float* B2 = sm + 21504;         // 2048
    const uint32_t As_u = (uint32_t)__cvta_generic_to_shared(As);
    const uint32_t B1_u = (uint32_t)__cvta_generic_to_shared(B1);
    const uint32_t B2_u = (uint32_t)__cvta_generic_to_shared(B2);

    const int tid = threadIdx.x, lane = tid & 31, w = tid >> 5;
    const int r = lane >> 2, cq = lane & 3;
    const int m0 = blockIdx.x * 128;  // M_F % 128 == 0

    {
        const float* src = g_xt + (size_t)(m0 + tid) * 64;
        uint32_t dst = As_u + (uint32_t)(tid * 68) * 4u;
        #pragma unroll
        for (int c4 = 0; c4 < 16; c4++) cp16(dst + c4 * 16, src + c4 * 4, 16);
        const float* b1s = g_Bd1 + tid * 4;
        #pragma unroll
        for (int i = 0; i < 8; i++)
            cp16(B1_u + (uint32_t)(tid * 16) + i * 2048, b1s + i * 512, 16);
        const float* b2s = g_Bd2 + tid * 4;
        #pragma unroll
        for (int i = 0; i < 4; i++)
            cp16(B2_u + (uint32_t)(tid * 16) + i * 2048, b2s + i * 512, 16);
    }
    cp_commit();
    asm volatile("cp.async.wait_group 0;");
    __syncthreads();

    // phase 1: As @ B1 + bd1 -> relu -> Cs
    {
        float acc[2][8][4];
        #pragma unroll
        for (int nf = 0; nf < 8; nf++) {
            float blo = __ldg(bd1 + nf * 8 + cq * 2);
            float bhi = __ldg(bd1 + nf * 8 + cq * 2 + 1);
            #pragma unroll
            for (int mf = 0; mf < 2; mf++) {
                acc[mf][nf][0] = blo; acc[mf][nf][1] = bhi;
                acc[mf][nf][2] = blo; acc[mf][nf][3] = bhi;
            }
        }
        const float* Ab = As + w * 32 * 68;
        #pragma unroll
        for (int ks = 0; ks < 8; ks++) {
            uint32_t a[2][4];
            #pragma unroll
            for (int mf = 0; mf < 2; mf++) {
                const float* ap = Ab + (mf * 16 + r) * 68 + ks * 8 + cq;
                a[mf][0] = f2tf(ap[0]);
                a[mf][1] = f2tf(ap[8 * 68]);
                a[mf][2] = f2tf(ap[4]);
                a[mf][3] = f2tf(ap[8 * 68 + 4]);
            }
            #pragma unroll
            for (int nf = 0; nf < 8; nf++) {
                uint2 bv = *(const uint2*)(B1 + (ks * 8 + nf) * 64 + lane * 2);
                uint32_t b[2] = {bv.x, bv.y};
                mma_tf32(acc[0][nf], a[0], b);
                mma_tf32(acc[1][nf], a[1], b);
            }
        }
        #pragma unroll
        for (int mf = 0; mf < 2; mf++) {
            int rl = w * 32 + mf * 16 + r;
            #pragma unroll
            for (int nf = 0; nf < 8; nf++) {
                *(float2*)(Cs + rl * 68 + nf * 8 + cq * 2) =
                    make_float2(fmaxf(acc[mf][nf][0], 0.f), fmaxf(acc[mf][nf][1], 0.f));
                *(float2*)(Cs + (rl + 8) * 68 + nf * 8 + cq * 2) =
                    make_float2(fmaxf(acc[mf][nf][2], 0.f), fmaxf(acc[mf][nf][3], 0.f));
            }
        }
    }
    __syncthreads();

    // phase 2: Cs @ B2 + bd2 + xup -> out
    {
        float acc[2][4][4];
        #pragma unroll
        for (int nf = 0; nf < 4; nf++) {
            float blo = __ldg(bd2 + nf * 8 + cq * 2);
            float bhi = __ldg(bd2 + nf * 8 + cq * 2 + 1);
            #pragma unroll
            for (int mf = 0; mf < 2; mf++) {
                acc[mf][nf][0] = blo; acc[mf][nf][1] = bhi;
                acc[mf][nf][2] = blo; acc[mf][nf][3] = bhi;
            }
        }
        const float* Ab = Cs + w * 32 * 68;
        #pragma unroll
        for (int ks = 0; ks < 8; ks++) {
            uint32_t a[2][4];
            #pragma unroll
            for (int mf = 0; mf < 2; mf++) {
                const float* ap = Ab + (mf * 16 + r) * 68 + ks * 8 + cq;
                a[mf][0] = f2tf(ap[0]);
                a[mf][1] = f2tf(ap[8 * 68]);
                a[mf][2] = f2tf(ap[4]);
                a[mf][3] = f2tf(ap[8 * 68 + 4]);
            }
            #pragma unroll
            for (int nf = 0; nf < 4; nf++) {
                uint2 bv = *(const uint2*)(B2 + (ks * 4 + nf) * 64 + lane * 2);
                uint32_t b[2] = {bv.x, bv.y};
                mma_tf32(acc[0][nf], a[0], b);
                mma_tf32(acc[1][nf], a[1], b);
            }
        }
        #pragma unroll
        for (int mf = 0; mf < 2; mf++) {
            int row = m0 + w * 32 + mf * 16 + r;
            #pragma unroll
            for (int nf = 0; nf < 4; nf++) {
                float2 u0 = *(const float2*)(xup + (size_t)row * 32 + nf * 8 + cq * 2);
                *(float2*)(out + (size_t)row * 32 + nf * 8 + cq * 2) =
                    make_float2(acc[mf][nf][0] + u0.x, acc[mf][nf][1] + u0.y);
                float2 u1 = *(const float2*)(xup + (size_t)(row + 8) * 32 + nf * 8 + cq * 2);
                *(float2*)(out + (size_t)(row + 8) * 32 + nf * 8 + cq * 2) =
                    make_float2(acc[mf][nf][2] + u1.x, acc[mf][nf][3] + u1.y);
            }
        }
    }
}

// ---------------- launch -------------------------------------------------
extern "C" void kernel_launch(void* const* d_in, const int* in_sizes, int n_in,
                              void* d_out, int out_size)
{
    const float* feats  = (const float*)d_in[0];
    const float* xup    = (const float*)d_in[1];
    const int*   nbr    = (const int*)  d_in[2];
    const int*   parent = (const int*)  d_in[3];
    const int*   off    = (const int*)  d_in[4];
    const float* W1  = (const float*)d_in[5];
    const float* b1  = (const float*)d_in[6];
    const float* W2  = (const float*)d_in[7];
    const float* b2  = (const float*)d_in[8];
    const float* W3  = (const float*)d_in[9];
    const float* b3  = (const float*)d_in[10];
    const float* Wt  = (const float*)d_in[11];
    const float* bt  = (const float*)d_in[12];
    const float* Wd1 = (const float*)d_in[13];
    const float* bd1 = (const float*)d_in[14];
    const float* Wd2 = (const float*)d_in[15];
    const float* bd2 = (const float*)d_in[16];
    float* out = (float*)d_out;

    float *h1, *h2, *bs1, *bs2, *bs3, *btb, *bd1b, *bd2b;
    cudaGetSymbolAddress((void**)&h1,   g_h1);
    cudaGetSymbolAddress((void**)&h2,   g_h2);
    cudaGetSymbolAddress((void**)&bs1,  g_Bs1);
    cudaGetSymbolAddress((void**)&bs2,  g_Bs2);
    cudaGetSymbolAddress((void**)&bs3,  g_Bs3);
    cudaGetSymbolAddress((void**)&btb,  g_Bt);
    cudaGetSymbolAddress((void**)&bd1b, g_Bd1);
    cudaGetSymbolAddress((void**)&bd2b, g_Bd2);

    const int SMEM32 = (2 * 128 * 36 + 2 * 32 * 64) * 4;   // 53248
    const int SMEM64 = (2 * 128 * 68 + 2 * 64 * 64) * 4;   // 102400
    const int SMEMT  = (128 * 68 + 64 * 64) * 4 + 128 * 4; // 51712
    const int SMEMD  = (8704 + 8704 + 4096 + 2048) * 4;    // 94208

    cudaFuncSetAttribute(conv3_mma<32>, cudaFuncAttributeMaxDynamicSharedMemorySize, SMEM32);
    cudaFuncSetAttribute(conv3_mma<64>, cudaFuncAttributeMaxDynamicSharedMemorySize, SMEM64);
    cudaFuncSetAttribute(tconv_mma,     cudaFuncAttributeMaxDynamicSharedMemorySize, SMEMT);
    cudaFuncSetAttribute(decoder_mma,   cudaFuncAttributeMaxDynamicSharedMemorySize, SMEMD);

    // weight shuffles (per-launch, deterministic)
    prep_shuffle<<<(27 * 32 * 64 + 255) / 256, 256>>>(W1,  bs1,  27 * 32 * 64, 32, 64);
    prep_shuffle<<<(27 * 64 * 64 + 255) / 256, 256>>>(W2,  bs2,  27 * 64 * 64, 64, 64);
    prep_shuffle<<<(27 * 64 * 64 + 255) / 256, 256>>>(W3,  bs3,  27 * 64 * 64, 64, 64);
    prep_shuffle<<<( 8 * 64 * 64 + 255) / 256, 256>>>(Wt,  btb,   8 * 64 * 64, 64, 64);
    prep_shuffle<<<(     64 * 64 + 255) / 256, 256>>>(Wd1, bd1b,      64 * 64, 64, 64);
    prep_shuffle<<<(     64 * 32 + 255) / 256, 256>>>(Wd2, bd2b,      64 * 32, 64, 32);

    grp_zero_kernel<<<1, 32>>>();
    grp_build_kernel<<<(M_F + 255) / 256, 256>>>(off);

    const int conv_grid = (N_C + 127) / 128;   // 782
    const int m_tiles   = M_F / 128;           // 3125

    conv3_mma<32><<<conv_grid, 128, SMEM32>>>(feats, nbr, bs1, b1, h1);
    conv3_mma<64><<<conv_grid, 128, SMEM64>>>(h1,    nbr, bs2, b2, h2);
    conv3_mma<64><<<conv_grid, 128, SMEM64>>>(h2,    nbr, bs3, b3, h1);

    tconv_mma<<<dim3(m_tiles, 8), 128, SMEMT>>>(bt, parent);

    decoder_mma<<<m_tiles, 128, SMEMD>>>(bd1, bd2, xup, out);
}

// round 4
// speedup vs baseline: 3.3140x; 1.1159x over previous
#include <cuda_runtime.h>
#include <cstdint>
#include <cstddef>

#define N_C   100000
#define M_F   400000

// ---------------- scratch (static device globals; no runtime alloc) -------
__device__ float g_fin[(size_t)N_C * 32];          // tf32-converted input feats
__device__ float g_h1[(size_t)N_C * 64];
__device__ float g_h2[(size_t)N_C * 64];
__device__ int   g_cnt[8];
__device__ int   g_tb[9];                          // tile-base prefix (+total)
__device__ int   g_grp[(size_t)8 * M_F];
// fragment-shuffled tf32 weights
__device__ float g_Bs1[27 * 32 * 64];
__device__ float g_Bs2[27 * 64 * 64];
__device__ float g_Bs3[27 * 64 * 64];
__device__ float g_Bt [ 8 * 64 * 64];
__device__ float g_Bd1[64 * 64];
__device__ float g_Bd2[64 * 32];

// segment sizes for the merged prep kernel
#define C_FE (N_C * 32)
#define C_S1 (27 * 32 * 64)
#define C_S2 (27 * 64 * 64)
#define C_S3 (27 * 64 * 64)
#define C_ST ( 8 * 64 * 64)
#define C_D1 (64 * 64)
#define C_D2 (64 * 32)
#define C_TOT (C_FE + C_S1 + C_S2 + C_S3 + C_ST + C_D1 + C_D2)

// ---------------- small helpers ------------------------------------------
__device__ __forceinline__ uint32_t f2tf(float f) {
    uint32_t u;
    asm("cvt.rna.tf32.f32 %0, %1;" : "=r"(u) : "f"(f));
    return u;
}
__device__ __forceinline__ void cp16(uint32_t dst, const void* src, int bytes) {
    asm volatile("cp.async.cg.shared.global [%0], [%1], 16, %2;"
                 :: "r"(dst), "l"(src), "r"(bytes));
}
__device__ __forceinline__ void cp_commit() {
    asm volatile("cp.async.commit_group;");
}
__device__ __forceinline__ void mma_tf32(float* c, const uint32_t* a, const uint32_t* b) {
    asm volatile("mma.sync.aligned.m16n8k8.row.col.f32.tf32.tf32.f32 "
                 "{%0,%1,%2,%3}, {%4,%5,%6,%7}, {%8,%9}, {%0,%1,%2,%3};"
                 : "+f"(c[0]), "+f"(c[1]), "+f"(c[2]), "+f"(c[3])
                 : "r"(a[0]), "r"(a[1]), "r"(a[2]), "r"(a[3]),
                   "r"(b[0]), "r"(b[1]));
}

// ---------------- merged prep: feats cvt + 6 weight shuffles + cnt zero ---
__device__ __forceinline__ void shuf(float* __restrict__ out, const float* __restrict__ W,
                                     int idx, int CIN, int COUT) {
    int reg  = idx & 1;
    int lane = (idx >> 1) & 31;
    int nfq  = idx >> 6;
    int NF   = COUT >> 3;
    int nf   = nfq % NF;
    int kks  = nfq / NF;
    int KSn  = CIN >> 3;
    int ks   = kks % KSn;
    int k    = kks / KSn;
    int ic   = ks * 8 + reg * 4 + (lane & 3);
    int oc   = nf * 8 + (lane >> 2);
    out[idx] = __uint_as_float(f2tf(__ldg(W + ((size_t)k * CIN + ic) * COUT + oc)));
}

__global__ void prep_all(const float* __restrict__ feats,
                         const float* __restrict__ W1, const float* __restrict__ W2,
                         const float* __restrict__ W3, const float* __restrict__ Wt,
                         const float* __restrict__ Wd1, const float* __restrict__ Wd2)
{
    if (blockIdx.x == 0 && threadIdx.x < 8) g_cnt[threadIdx.x] = 0;
    int id = blockIdx.x * 256 + threadIdx.x;
    if (id < C_FE) { g_fin[id] = __uint_as_float(f2tf(__ldg(feats + id))); return; }
    id -= C_FE;
    if (id < C_S1) { shuf(g_Bs1, W1, id, 32, 64); return; }
    id -= C_S1;
    if (id < C_S2) { shuf(g_Bs2, W2, id, 64, 64); return; }
    id -= C_S2;
    if (id < C_S3) { shuf(g_Bs3, W3, id, 64, 64); return; }
    id -= C_S3;
    if (id < C_ST) { shuf(g_Bt,  Wt, id, 64, 64); return; }
    id -= C_ST;
    if (id < C_D1) { shuf(g_Bd1, Wd1, id, 64, 64); return; }
    id -= C_D1;
    if (id < C_D2) { shuf(g_Bd2, Wd2, id, 64, 32); return; }
}

__global__ void grp_build_kernel(const int* __restrict__ off) {
    int m = blockIdx.x * 256 + threadIdx.x;
    if (m < M_F) {
        int k = off[m] & 7;
        int pos = atomicAdd(&g_cnt[k], 1);
        g_grp[(size_t)k * M_F + pos] = m;
    }
}

__global__ void grp_tiles_kernel() {
    if (threadIdx.x == 0) {
        int base = 0;
        #pragma unroll
        for (int k = 0; k < 8; k++) { g_tb[k] = base; base += (g_cnt[k] + 127) >> 7; }
        g_tb[8] = base;
    }
}

// ---------------- sparse 3x3x3 conv via mma.sync tf32 --------------------
// A data in global is ALREADY tf32 bit-patterns -> no cvt in inner loop.
template<int CIN>
__global__ void __launch_bounds__(128)
conv3_mma(const float* __restrict__ x, const int* __restrict__ nbr,
          const float* __restrict__ Bw, const float* __restrict__ bias,
          float* __restrict__ out)
{
    constexpr int SAp  = CIN + 4;
    constexpr int KS   = CIN / 8;
    constexpr int ABUF = 128 * SAp;
    constexpr int BBUF = CIN * 64;
    extern __shared__ float sm[];
    float* As = sm;
    float* Bs = sm + 2 * ABUF;
    const uint32_t As_u = (uint32_t)__cvta_generic_to_shared(As);
    const uint32_t Bs_u = (uint32_t)__cvta_generic_to_shared(Bs);

    const int tid  = threadIdx.x;
    const int lane = tid & 31;
    const int w    = tid >> 5;
    const int v0   = blockIdx.x * 128;
    const int r    = lane >> 2;
    const int cq   = lane & 3;

    float acc[2][8][4];
    #pragma unroll
    for (int nf = 0; nf < 8; nf++) {
        float blo = __ldg(bias + nf * 8 + cq * 2);
        float bhi = __ldg(bias + nf * 8 + cq * 2 + 1);
        #pragma unroll
        for (int mf = 0; mf < 2; mf++) {
            acc[mf][nf][0] = blo; acc[mf][nf][1] = bhi;
            acc[mf][nf][2] = blo; acc[mf][nf][3] = bhi;
        }
    }

    const int  gv  = v0 + tid;
    const bool vok = gv < N_C;

    auto stage = [&](int k, int buf) {
        int n = vok ? __ldg(nbr + (size_t)gv * 27 + k) : N_C;
        int bytes = (n < N_C) ? 16 : 0;
        const float* src = x + (size_t)(n < N_C ? n : 0) * CIN;
        uint32_t dst = As_u + (uint32_t)(buf * ABUF + tid * SAp) * 4u;
        #pragma unroll
        for (int c4 = 0; c4 < CIN / 4; c4++)
            cp16(dst + c4 * 16, src + c4 * 4, bytes);
        const float* bsrc = Bw + (size_t)k * BBUF + tid * 4;
        uint32_t bdst = Bs_u + (uint32_t)(buf * BBUF + tid * 4) * 4u;
        #pragma unroll
        for (int i = 0; i < BBUF / 512; i++)
            cp16(bdst + i * 2048, bsrc + i * 512, 16);
    };

    stage(0, 0);
    cp_commit();
    int cbuf = 0;
    #pragma unroll 1
    for (int k = 0; k < 27; k++) {
        if (k < 26) {
            stage(k + 1, cbuf ^ 1);
            cp_commit();
            asm volatile("cp.async.wait_group 1;");
        } else {
            asm volatile("cp.async.wait_group 0;");
        }
        __syncthreads();

        const float* Ab = As + cbuf * ABUF + w * 32 * SAp;
        const float* Bb = Bs + cbuf * BBUF;
        #pragma unroll
        for (int ks = 0; ks < KS; ks++) {
            uint32_t a[2][4];
            #pragma unroll
            for (int mf = 0; mf < 2; mf++) {
                const float* ap = Ab + (mf * 16 + r) * SAp + ks * 8 + cq;
                a[mf][0] = __float_as_uint(ap[0]);
                a[mf][1] = __float_as_uint(ap[8 * SAp]);
                a[mf][2] = __float_as_uint(ap[4]);
                a[mf][3] = __float_as_uint(ap[8 * SAp + 4]);
            }
            #pragma unroll
            for (int nf = 0; nf < 8; nf++) {
                uint2 bv = *(const uint2*)(Bb + (ks * 8 + nf) * 64 + lane * 2);
                uint32_t b[2] = {bv.x, bv.y};
                mma_tf32(acc[0][nf], a[0], b);
                mma_tf32(acc[1][nf], a[1], b);
            }
        }
        __syncthreads();
        cbuf ^= 1;
    }

    // epilogue: relu + tf32-convert at store (identical rounding to cvt-at-load)
    #pragma unroll
    for (int mf = 0; mf < 2; mf++) {
        int row = v0 + w * 32 + mf * 16 + r;
        if (row < N_C) {
            float* op = out + (size_t)row * 64 + cq * 2;
            #pragma unroll
            for (int nf = 0; nf < 8; nf++) {
                float2 v = make_float2(
                    __uint_as_float(f2tf(fmaxf(acc[mf][nf][0], 0.f))),
                    __uint_as_float(f2tf(fmaxf(acc[mf][nf][1], 0.f))));
                *(float2*)(op + nf * 8) = v;
            }
        }
        if (row + 8 < N_C) {
            float* op = out + (size_t)(row + 8) * 64 + cq * 2;
            #pragma unroll
            for (int nf = 0; nf < 8; nf++) {
                float2 v = make_float2(
                    __uint_as_float(f2tf(fmaxf(acc[mf][nf][2], 0.f))),
                    __uint_as_float(f2tf(fmaxf(acc[mf][nf][3], 0.f))));
                *(float2*)(op + nf * 8) = v;
            }
        }
    }
}

// ---------------- fused tconv + decoder -----------------------------------
// Flat tiling: block t -> (k, r0) via g_tb prefix. Three chained GEMMs:
//   tconv (A=gathered parents, B=Wt[k]) -> relu -> As
//   d1    (A=As, B=Wd1)                 -> relu -> As
//   d2    (A=As, B=Wd2) + bd2 + xup[m]  -> out[m]  (scattered)
__global__ void __launch_bounds__(128)
tconv_dec_mma(const float* __restrict__ bt, const float* __restrict__ bd1,
              const float* __restrict__ bd2, const int* __restrict__ parent,
              const float* __restrict__ xup, float* __restrict__ out)
{
    extern __shared__ float sm[];
    float* As = sm;                        // 128*68 = 8704
    float* Bt = sm + 8704;                 // 4096
    float* B1 = Bt + 4096;                 // 4096
    float* B2 = B1 + 4096;                 // 2048
    int*   s_m = (int*)(B2 + 2048);        // 128
    const uint32_t As_u = (uint32_t)__cvta_generic_to_shared(As);
    const uint32_t Bt_u = (uint32_t)__cvta_generic_to_shared(Bt);
    const uint32_t B1_u = (uint32_t)__cvta_generic_to_shared(B1);
    const uint32_t B2_u = (uint32_t)__cvta_generic_to_shared(B2);

    const int t = blockIdx.x;
    if (t >= g_tb[8]) return;
    int k = 0;
    #pragma unroll
    for (int i = 1; i < 8; i++) k += (t >= g_tb[i]);
    const int r0  = (t - g_tb[k]) << 7;
    const int cnt = g_cnt[k];

    const int tid = threadIdx.x, lane = tid & 31, w = tid >> 5;
    const int r = lane >> 2, cq = lane & 3;

    {   // stage: gathered A rows + all three weight tiles
        int rr = r0 + tid;
        int m = (rr < cnt) ? g_grp[(size_t)k * M_F + rr] : -1;
        s_m[tid] = m;
        int p = (m >= 0) ? __ldg(parent + m) : N_C;
        int bytes = (p < N_C) ? 16 : 0;
        const float* src = g_h1 + (size_t)(p < N_C ? p : 0) * 64;
        uint32_t dst = As_u + (uint32_t)(tid * 68) * 4u;
        #pragma unroll
        for (int c4 = 0; c4 < 16; c4++) cp16(dst + c4 * 16, src + c4 * 4, bytes);
        const float* bsrc = g_Bt + (size_t)k * 4096 + tid * 4;
        #pragma unroll
        for (int i = 0; i < 8; i++)
            cp16(Bt_u + (uint32_t)(tid * 16) + i * 2048, bsrc + i * 512, 16);
        const float* b1s = g_Bd1 + tid * 4;
        #pragma unroll
        for (int i = 0; i < 8; i++)
            cp16(B1_u + (uint32_t)(tid * 16) + i * 2048, b1s + i * 512, 16);
        const float* b2s = g_Bd2 + tid * 4;
        #pragma unroll
        for (int i = 0; i < 4; i++)
            cp16(B2_u + (uint32_t)(tid * 16) + i * 2048, b2s + i * 512, 16);
    }
    cp_commit();
    asm volatile("cp.async.wait_group 0;");
    __syncthreads();

    // ---- GEMM helper over full 64-col B, 8 k-steps ----
    auto gemm64 = [&](const float* Bm, const float* bias, float acc[2][8][4]) {
        #pragma unroll
        for (int nf = 0; nf < 8; nf++) {
            float blo = __ldg(bias + nf * 8 + cq * 2);
            float bhi = __ldg(bias + nf * 8 + cq * 2 + 1);
            #pragma unroll
            for (int mf = 0; mf < 2; mf++) {
                acc[mf][nf][0] = blo; acc[mf][nf][1] = bhi;
                acc[mf][nf][2] = blo; acc[mf][nf][3] = bhi;
            }
        }
        const float* Ab = As + w * 32 * 68;
        #pragma unroll
        for (int ks = 0; ks < 8; ks++) {
            uint32_t a[2][4];
            #pragma unroll
            for (int mf = 0; mf < 2; mf++) {
                const float* ap = Ab + (mf * 16 + r) * 68 + ks * 8 + cq;
                a[mf][0] = __float_as_uint(ap[0]);
                a[mf][1] = __float_as_uint(ap[8 * 68]);
                a[mf][2] = __float_as_uint(ap[4]);
                a[mf][3] = __float_as_uint(ap[8 * 68 + 4]);
            }
            #pragma unroll
            for (int nf = 0; nf < 8; nf++) {
                uint2 bv = *(const uint2*)(Bm + (ks * 8 + nf) * 64 + lane * 2);
                uint32_t b[2] = {bv.x, bv.y};
                mma_tf32(acc[0][nf], a[0], b);
                mma_tf32(acc[1][nf], a[1], b);
            }
        }
    };
    auto relu_store = [&](float acc[2][8][4]) {
        __syncthreads();                 // all warps done reading As
        #pragma unroll
        for (int mf = 0; mf < 2; mf++) {
            int rl = w * 32 + mf * 16 + r;
            #pragma unroll
            for (int nf = 0; nf < 8; nf++) {
                *(float2*)(As + rl * 68 + nf * 8 + cq * 2) = make_float2(
                    __uint_as_float(f2tf(fmaxf(acc[mf][nf][0], 0.f))),
                    __uint_as_float(f2tf(fmaxf(acc[mf][nf][1], 0.f))));
                *(float2*)(As + (rl + 8) * 68 + nf * 8 + cq * 2) = make_float2(
                    __uint_as_float(f2tf(fmaxf(acc[mf][nf][2], 0.f))),
                    __uint_as_float(f2tf(fmaxf(acc[mf][nf][3], 0.f))));
            }
        }
        __syncthreads();
    };

    float acc[2][8][4];
    gemm64(Bt, bt, acc);       // tconv
    relu_store(acc);
    gemm64(B1, bd1, acc);      // decoder layer 1
    relu_store(acc);

    // decoder layer 2: 64 -> 32, + residual, scattered store
    {
        float a2[2][4][4];
        #pragma unroll
        for (int nf = 0; nf < 4; nf++) {
            float blo = __ldg(bd2 + nf * 8 + cq * 2);
            float bhi = __ldg(bd2 + nf * 8 + cq * 2 + 1);
            #pragma unroll
            for (int mf = 0; mf < 2; mf++) {
                a2[mf][nf][0] = blo; a2[mf][nf][1] = bhi;
                a2[mf][nf][2] = blo; a2[mf][nf][3] = bhi;
            }
        }
        const float* Ab = As + w * 32 * 68;
        #pragma unroll
        for (int ks = 0; ks < 8; ks++) {
            uint32_t a[2][4];
            #pragma unroll
            for (int mf = 0; mf < 2; mf++) {
                const float* ap = Ab + (mf * 16 + r) * 68 + ks * 8 + cq;
                a[mf][0] = __float_as_uint(ap[0]);
                a[mf][1] = __float_as_uint(ap[8 * 68]);
                a[mf][2] = __float_as_uint(ap[4]);
                a[mf][3] = __float_as_uint(ap[8 * 68 + 4]);
            }
            #pragma unroll
            for (int nf = 0; nf < 4; nf++) {
                uint2 bv = *(const uint2*)(B2 + (ks * 4 + nf) * 64 + lane * 2);
                uint32_t b[2] = {bv.x, bv.y};
                mma_tf32(a2[0][nf], a[0], b);
                mma_tf32(a2[1][nf], a[1], b);
            }
        }
        #pragma unroll
        for (int mf = 0; mf < 2; mf++) {
            int rl = w * 32 + mf * 16 + r;
            int m = s_m[rl];
            if (m >= 0) {
                #pragma unroll
                for (int nf = 0; nf < 4; nf++) {
                    float2 u = *(const float2*)(xup + (size_t)m * 32 + nf * 8 + cq * 2);
                    *(float2*)(out + (size_t)m * 32 + nf * 8 + cq * 2) =
                        make_float2(a2[mf][nf][0] + u.x, a2[mf][nf][1] + u.y);
                }
            }
            int m2 = s_m[rl + 8];
            if (m2 >= 0) {
                #pragma unroll
                for (int nf = 0; nf < 4; nf++) {
                    float2 u = *(const float2*)(xup + (size_t)m2 * 32 + nf * 8 + cq * 2);
                    *(float2*)(out + (size_t)m2 * 32 + nf * 8 + cq * 2) =
                        make_float2(a2[mf][nf][2] + u.x, a2[mf][nf][3] + u.y);
                }
            }
        }
    }
}

// ---------------- launch -------------------------------------------------
extern "C" void kernel_launch(void* const* d_in, const int* in_sizes, int n_in,
                              void* d_out, int out_size)
{
    const float* feats  = (const float*)d_in[0];
    const float* xup    = (const float*)d_in[1];
    const int*   nbr    = (const int*)  d_in[2];
    const int*   parent = (const int*)  d_in[3];
    const int*   off    = (const int*)  d_in[4];
    const float* W1  = (const float*)d_in[5];
    const float* b1  = (const float*)d_in[6];
    const float* W2  = (const float*)d_in[7];
    const float* b2  = (const float*)d_in[8];
    const float* W3  = (const float*)d_in[9];
    const float* b3  = (const float*)d_in[10];
    const float* Wt  = (const float*)d_in[11];
    const float* bt  = (const float*)d_in[12];
    const float* Wd1 = (const float*)d_in[13];
    const float* bd1 = (const float*)d_in[14];
    const float* Wd2 = (const float*)d_in[15];
    const float* bd2 = (const float*)d_in[16];
    float* out = (float*)d_out;

    float *fin, *h1, *h2, *bs1, *bs2, *bs3;
    cudaGetSymbolAddress((void**)&fin, g_fin);
    cudaGetSymbolAddress((void**)&h1,  g_h1);
    cudaGetSymbolAddress((void**)&h2,  g_h2);
    cudaGetSymbolAddress((void**)&bs1, g_Bs1);
    cudaGetSymbolAddress((void**)&bs2, g_Bs2);
    cudaGetSymbolAddress((void**)&bs3, g_Bs3);

    const int SMEM32 = (2 * 128 * 36 + 2 * 32 * 64) * 4;   // 53248
    const int SMEM64 = (2 * 128 * 68 + 2 * 64 * 64) * 4;   // 102400
    const int SMEMF  = (8704 + 4096 + 4096 + 2048) * 4 + 128 * 4; // 76288

    cudaFuncSetAttribute(conv3_mma<32>, cudaFuncAttributeMaxDynamicSharedMemorySize, SMEM32);
    cudaFuncSetAttribute(conv3_mma<64>, cudaFuncAttributeMaxDynamicSharedMemorySize, SMEM64);
    cudaFuncSetAttribute(tconv_dec_mma, cudaFuncAttributeMaxDynamicSharedMemorySize, SMEMF);

    prep_all<<<(C_TOT + 255) / 256, 256>>>(feats, W1, W2, W3, Wt, Wd1, Wd2);
    grp_build_kernel<<<(M_F + 255) / 256, 256>>>(off);
    grp_tiles_kernel<<<1, 32>>>();

    const int conv_grid = (N_C + 127) / 128;   // 782
    conv3_mma<32><<<conv_grid, 128, SMEM32>>>(fin, nbr, bs1, b1, h1);
    conv3_mma<64><<<conv_grid, 128, SMEM64>>>(h1,  nbr, bs2, b2, h2);
    conv3_mma<64><<<conv_grid, 128, SMEM64>>>(h2,  nbr, bs3, b3, h1);

    const int max_tiles = (M_F + 127) / 128 + 7;   // 3132
    tconv_dec_mma<<<max_tiles, 128, SMEMF>>>(bt, bd1, bd2, parent, xup, out);
}

// round 5
// speedup vs baseline: 5.0009x; 1.5090x over previous
#include <cuda_runtime.h>
#include <cuda_fp16.h>
#include <cstdint>
#include <cstddef>

#define N_C   100000
#define M_F   400000

// ---------------- scratch (static device globals; no runtime alloc) -------
__device__ __half g_finh[(size_t)N_C * 32];        // fp16 input feats
__device__ __half g_ha[(size_t)N_C * 64];          // conv1 out (fp16)
__device__ __half g_hb[(size_t)N_C * 64];          // conv2 out (fp16)
__device__ float  g_h1[(size_t)N_C * 64];          // conv3 out (tf32 bits, for tconv)
__device__ int    g_cnt[8];
__device__ int    g_tb[9];
__device__ int    g_grp[(size_t)8 * M_F];
// fp16 fragment-shuffled conv weights (uint32 = half2)
__device__ uint32_t g_B1h[27 * 2 * 512];           // CIN=32: KS=2
__device__ uint32_t g_B2h[27 * 4 * 512];           // CIN=64: KS=4
__device__ uint32_t g_B3h[27 * 4 * 512];
// tf32 fragment-shuffled weights (tconv + decoder)
__device__ float g_Bt [ 8 * 64 * 64];
__device__ float g_Bd1[64 * 64];
__device__ float g_Bd2[64 * 32];

// prep segment sizes
#define C_FE (N_C * 32)
#define C_B1 (27 * 2 * 512)
#define C_B2 (27 * 4 * 512)
#define C_B3 (27 * 4 * 512)
#define C_ST ( 8 * 64 * 64)
#define C_D1 (64 * 64)
#define C_D2 (64 * 32)
#define C_TOT (C_FE + C_B1 + C_B2 + C_B3 + C_ST + C_D1 + C_D2)

// ---------------- small helpers ------------------------------------------
__device__ __forceinline__ uint32_t f2tf(float f) {
    uint32_t u;
    asm("cvt.rna.tf32.f32 %0, %1;" : "=r"(u) : "f"(f));
    return u;
}
__device__ __forceinline__ void cp16(uint32_t dst, const void* src, int bytes) {
    asm volatile("cp.async.cg.shared.global [%0], [%1], 16, %2;"
                 :: "r"(dst), "l"(src), "r"(bytes));
}
__device__ __forceinline__ void cp_commit() {
    asm volatile("cp.async.commit_group;");
}
__device__ __forceinline__ void mma_tf32(float* c, const uint32_t* a, const uint32_t* b) {
    asm volatile("mma.sync.aligned.m16n8k8.row.col.f32.tf32.tf32.f32 "
                 "{%0,%1,%2,%3}, {%4,%5,%6,%7}, {%8,%9}, {%0,%1,%2,%3};"
                 : "+f"(c[0]), "+f"(c[1]), "+f"(c[2]), "+f"(c[3])
                 : "r"(a[0]), "r"(a[1]), "r"(a[2]), "r"(a[3]),
                   "r"(b[0]), "r"(b[1]));
}
__device__ __forceinline__ void mma_f16(float* c, const uint32_t* a,
                                        uint32_t b0, uint32_t b1) {
    asm volatile("mma.sync.aligned.m16n8k16.row.col.f32.f16.f16.f32 "
                 "{%0,%1,%2,%3}, {%4,%5,%6,%7}, {%8,%9}, {%0,%1,%2,%3};"
                 : "+f"(c[0]), "+f"(c[1]), "+f"(c[2]), "+f"(c[3])
                 : "r"(a[0]), "r"(a[1]), "r"(a[2]), "r"(a[3]),
                   "r"(b0), "r"(b1));
}
__device__ __forceinline__ void ldm4(uint32_t* a, uint32_t saddr) {
    asm volatile("ldmatrix.sync.aligned.m8n8.x4.shared.b16 {%0,%1,%2,%3}, [%4];"
                 : "=r"(a[0]), "=r"(a[1]), "=r"(a[2]), "=r"(a[3]) : "r"(saddr));
}
__device__ __forceinline__ uint32_t pack2(float a, float b) {
    __half2 h = __floats2half2_rn(a, b);
    return *(uint32_t*)&h;
}

// ---------------- prep: feats->fp16, weight shuffles, cnt zero ------------
__device__ __forceinline__ void shuf_tf(float* __restrict__ out, const float* __restrict__ W,
                                        int idx, int CIN, int COUT) {
    int reg  = idx & 1;
    int lane = (idx >> 1) & 31;
    int nfq  = idx >> 6;
    int NF   = COUT >> 3;
    int nf   = nfq % NF;
    int kks  = nfq / NF;
    int KSn  = CIN >> 3;
    int ks   = kks % KSn;
    int k    = kks / KSn;
    int ic   = ks * 8 + reg * 4 + (lane & 3);
    int oc   = nf * 8 + (lane >> 2);
    out[idx] = __uint_as_float(f2tf(__ldg(W + ((size_t)k * CIN + ic) * COUT + oc)));
}
// fp16 B-fragment order for m16n8k16: uint id -> (k, ks, nf, lane, reg)
__device__ __forceinline__ void shuf_h(uint32_t* __restrict__ out, const float* __restrict__ W,
                                       int id, int CIN) {
    int reg  = id & 1;
    int lane = (id >> 1) & 31;
    int nf   = (id >> 6) & 7;
    int rest = id >> 9;
    int KS   = CIN >> 4;
    int ks   = rest % KS;
    int k    = rest / KS;
    int kk   = ks * 16 + (lane & 3) * 2 + reg * 8;
    int oc   = nf * 8 + (lane >> 2);
    float f0 = __ldg(W + ((size_t)k * CIN + kk) * 64 + oc);
    float f1 = __ldg(W + ((size_t)k * CIN + kk + 1) * 64 + oc);
    out[id] = pack2(f0, f1);
}

__global__ void prep_all(const float* __restrict__ feats,
                         const float* __restrict__ W1, const float* __restrict__ W2,
                         const float* __restrict__ W3, const float* __restrict__ Wt,
                         const float* __restrict__ Wd1, const float* __restrict__ Wd2)
{
    if (blockIdx.x == 0 && threadIdx.x < 8) g_cnt[threadIdx.x] = 0;
    int id = blockIdx.x * 256 + threadIdx.x;
    if (id < C_FE) { g_finh[id] = __float2half_rn(__ldg(feats + id)); return; }
    id -= C_FE;
    if (id < C_B1) { shuf_h(g_B1h, W1, id, 32); return; }
    id -= C_B1;
    if (id < C_B2) { shuf_h(g_B2h, W2, id, 64); return; }
    id -= C_B2;
    if (id < C_B3) { shuf_h(g_B3h, W3, id, 64); return; }
    id -= C_B3;
    if (id < C_ST) { shuf_tf(g_Bt,  Wt,  id, 64, 64); return; }
    id -= C_ST;
    if (id < C_D1) { shuf_tf(g_Bd1, Wd1, id, 64, 64); return; }
    id -= C_D1;
    if (id < C_D2) { shuf_tf(g_Bd2, Wd2, id, 64, 32); return; }
}

__global__ void grp_build_kernel(const int* __restrict__ off) {
    int m = blockIdx.x * 256 + threadIdx.x;
    if (m < M_F) {
        int k = off[m] & 7;
        int pos = atomicAdd(&g_cnt[k], 1);
        g_grp[(size_t)k * M_F + pos] = m;
    }
}
__global__ void grp_tiles_kernel() {
    if (threadIdx.x == 0) {
        int base = 0;
        #pragma unroll
        for (int k = 0; k < 8; k++) { g_tb[k] = base; base += (g_cnt[k] + 127) >> 7; }
        g_tb[8] = base;
    }
}

// ---------------- sparse 3x3x3 conv, fp16 mma (m16n8k16 + ldmatrix) ------
// Block 128 thr / 4 warps; tile 128 voxels x 64 out-ch; warp = 32 rows.
// HOUT: true -> fp16 output (next conv), false -> fp32 tf32-bits (tconv).
template<int CIN, bool HOUT>
__global__ void __launch_bounds__(128)
conv3_h(const __half* __restrict__ x, const int* __restrict__ nbr,
        const uint32_t* __restrict__ Bw, const float* __restrict__ bias,
        __half* __restrict__ outh, float* __restrict__ outf)
{
    constexpr int STR  = CIN + 8;            // halves per A row (144B / 80B)
    constexpr int KS   = CIN / 16;
    constexpr int ABYT = 128 * STR * 2;      // bytes per A buffer
    constexpr int BUNT = KS * 8 * 64;        // uints per B buffer
    extern __shared__ char smc[];
    __half*   As = (__half*)smc;
    uint32_t* Bs = (uint32_t*)(smc + 2 * ABYT);
    const uint32_t As_u = (uint32_t)__cvta_generic_to_shared(As);
    const uint32_t Bs_u = (uint32_t)__cvta_generic_to_shared(Bs);

    const int tid  = threadIdx.x;
    const int lane = tid & 31;
    const int w    = tid >> 5;
    const int v0   = blockIdx.x * 128;
    const int r    = lane >> 2;
    const int cq   = lane & 3;

    float acc[2][8][4];
    #pragma unroll
    for (int nf = 0; nf < 8; nf++) {
        float blo = __ldg(bias + nf * 8 + cq * 2);
        float bhi = __ldg(bias + nf * 8 + cq * 2 + 1);
        #pragma unroll
        for (int mf = 0; mf < 2; mf++) {
            acc[mf][nf][0] = blo; acc[mf][nf][1] = bhi;
            acc[mf][nf][2] = blo; acc[mf][nf][3] = bhi;
        }
    }

    const int  gv  = v0 + tid;
    const bool vok = gv < N_C;

    auto stage = [&](int k, int buf) {
        int n = vok ? __ldg(nbr + (size_t)gv * 27 + k) : N_C;
        int bytes = (n < N_C) ? 16 : 0;
        const __half* src = x + (size_t)(n < N_C ? n : 0) * CIN;
        uint32_t dst = As_u + (uint32_t)(buf * ABYT + tid * STR * 2);
        #pragma unroll
        for (int c = 0; c < CIN / 8; c++)
            cp16(dst + c * 16, src + c * 8, bytes);
        const uint32_t* bsrc = Bw + (size_t)k * BUNT + tid * 4;
        uint32_t bdst = Bs_u + (uint32_t)(buf * BUNT * 4 + tid * 16);
        #pragma unroll
        for (int i = 0; i < KS; i++)
            cp16(bdst + i * 2048, bsrc + i * 512, 16);
    };

    stage(0, 0);
    cp_commit();
    int cbuf = 0;
    #pragma unroll 1
    for (int k = 0; k < 27; k++) {
        if (k < 26) {
            stage(k + 1, cbuf ^ 1);
            cp_commit();
            asm volatile("cp.async.wait_group 1;");
        } else {
            asm volatile("cp.async.wait_group 0;");
        }
        __syncthreads();

        // ldmatrix lane address: rows w*32 + (lane&15) [+16 for mf=1],
        // col-halves ks*16 + (lane>>4)*8
        const uint32_t Ab = As_u + (uint32_t)(cbuf * ABYT) +
            (uint32_t)(((w * 32 + (lane & 15)) * STR + (lane >> 4) * 8) * 2);
        const uint32_t* Bb = Bs + cbuf * BUNT;
        #pragma unroll
        for (int ks = 0; ks < KS; ks++) {
            uint32_t a0[4], a1[4];
            ldm4(a0, Ab + ks * 32);
            ldm4(a1, Ab + 16 * STR * 2 + ks * 32);
            #pragma unroll
            for (int nf = 0; nf < 8; nf++) {
                uint2 bv = *(const uint2*)(Bb + (ks * 8 + nf) * 64 + lane * 2);
                mma_f16(acc[0][nf], a0, bv.x, bv.y);
                mma_f16(acc[1][nf], a1, bv.x, bv.y);
            }
        }
        __syncthreads();
        cbuf ^= 1;
    }

    #pragma unroll
    for (int mf = 0; mf < 2; mf++) {
        int row = v0 + w * 32 + mf * 16 + r;
        if (row < N_C) {
            if (HOUT) {
                uint32_t* op = (uint32_t*)(outh + (size_t)row * 64) + cq;
                #pragma unroll
                for (int nf = 0; nf < 8; nf++)
                    op[nf * 4] = pack2(fmaxf(acc[mf][nf][0], 0.f),
                                       fmaxf(acc[mf][nf][1], 0.f));
            } else {
                float* op = outf + (size_t)row * 64 + cq * 2;
                #pragma unroll
                for (int nf = 0; nf < 8; nf++)
                    *(float2*)(op + nf * 8) = make_float2(
                        __uint_as_float(f2tf(fmaxf(acc[mf][nf][0], 0.f))),
                        __uint_as_float(f2tf(fmaxf(acc[mf][nf][1], 0.f))));
            }
        }
        if (row + 8 < N_C) {
            if (HOUT) {
                uint32_t* op = (uint32_t*)(outh + (size_t)(row + 8) * 64) + cq;
                #pragma unroll
                for (int nf = 0; nf < 8; nf++)
                    op[nf * 4] = pack2(fmaxf(acc[mf][nf][2], 0.f),
                                       fmaxf(acc[mf][nf][3], 0.f));
            } else {
                float* op = outf + (size_t)(row + 8) * 64 + cq * 2;
                #pragma unroll
                for (int nf = 0; nf < 8; nf++)
                    *(float2*)(op + nf * 8) = make_float2(
                        __uint_as_float(f2tf(fmaxf(acc[mf][nf][2], 0.f))),
                        __uint_as_float(f2tf(fmaxf(acc[mf][nf][3], 0.f))));
            }
        }
    }
}

// ---------------- fused tconv + decoder (tf32, unchanged) -----------------
__global__ void __launch_bounds__(128)
tconv_dec_mma(const float* __restrict__ bt, const float* __restrict__ bd1,
              const float* __restrict__ bd2, const int* __restrict__ parent,
              const float* __restrict__ xup, float* __restrict__ out)
{
    extern __shared__ float sm[];
    float* As = sm;                        // 128*68 = 8704
    float* Bt = sm + 8704;                 // 4096
    float* B1 = Bt + 4096;                 // 4096
    float* B2 = B1 + 4096;                 // 2048
    int*   s_m = (int*)(B2 + 2048);        // 128
    const uint32_t As_u = (uint32_t)__cvta_generic_to_shared(As);
    const uint32_t Bt_u = (uint32_t)__cvta_generic_to_shared(Bt);
    const uint32_t B1_u = (uint32_t)__cvta_generic_to_shared(B1);
    const uint32_t B2_u = (uint32_t)__cvta_generic_to_shared(B2);

    const int t = blockIdx.x;
    if (t >= g_tb[8]) return;
    int k = 0;
    #pragma unroll
    for (int i = 1; i < 8; i++) k += (t >= g_tb[i]);
    const int r0  = (t - g_tb[k]) << 7;
    const int cnt = g_cnt[k];

    const int tid = threadIdx.x, lane = tid & 31, w = tid >> 5;
    const int r = lane >> 2, cq = lane & 3;

    {
        int rr = r0 + tid;
        int m = (rr < cnt) ? g_grp[(size_t)k * M_F + rr] : -1;
        s_m[tid] = m;
        int p = (m >= 0) ? __ldg(parent + m) : N_C;
        int bytes = (p < N_C) ? 16 : 0;
        const float* src = g_h1 + (size_t)(p < N_C ? p : 0) * 64;
        uint32_t dst = As_u + (uint32_t)(tid * 68) * 4u;
        #pragma unroll
        for (int c4 = 0; c4 < 16; c4++) cp16(dst + c4 * 16, src + c4 * 4, bytes);
        const float* bsrc = g_Bt + (size_t)k * 4096 + tid * 4;
        #pragma unroll
        for (int i = 0; i < 8; i++)
            cp16(Bt_u + (uint32_t)(tid * 16) + i * 2048, bsrc + i * 512, 16);
        const float* b1s = g_Bd1 + tid * 4;
        #pragma unroll
        for (int i = 0; i < 8; i++)
            cp16(B1_u + (uint32_t)(tid * 16) + i * 2048, b1s + i * 512, 16);
        const float* b2s = g_Bd2 + tid * 4;
        #pragma unroll
        for (int i = 0; i < 4; i++)
            cp16(B2_u + (uint32_t)(tid * 16) + i * 2048, b2s + i * 512, 16);
    }
    cp_commit();
    asm volatile("cp.async.wait_group 0;");
    __syncthreads();

    auto gemm64 = [&](const float* Bm, const float* bias, float acc[2][8][4]) {
        #pragma unroll
        for (int nf = 0; nf < 8; nf++) {
            float blo = __ldg(bias + nf * 8 + cq * 2);
            float bhi = __ldg(bias + nf * 8 + cq * 2 + 1);
            #pragma unroll
            for (int mf = 0; mf < 2; mf++) {
                acc[mf][nf][0] = blo; acc[mf][nf][1] = bhi;
                acc[mf][nf][2] = blo; acc[mf][nf][3] = bhi;
            }
        }
        const float* Ab = As + w * 32 * 68;
        #pragma unroll
        for (int ks = 0; ks < 8; ks++) {
            uint32_t a[2][4];
            #pragma unroll
            for (int mf = 0; mf < 2; mf++) {
                const float* ap = Ab + (mf * 16 + r) * 68 + ks * 8 + cq;
                a[mf][0] = __float_as_uint(ap[0]);
                a[mf][1] = __float_as_uint(ap[8 * 68]);
                a[mf][2] = __float_as_uint(ap[4]);
                a[mf][3] = __float_as_uint(ap[8 * 68 + 4]);
            }
            #pragma unroll
            for (int nf = 0; nf < 8; nf++) {
                uint2 bv = *(const uint2*)(Bm + (ks * 8 + nf) * 64 + lane * 2);
                uint32_t b[2] = {bv.x, bv.y};
                mma_tf32(acc[0][nf], a[0], b);
                mma_tf32(acc[1][nf], a[1], b);
            }
        }
    };
    auto relu_store = [&](float acc[2][8][4]) {
        __syncthreads();
        #pragma unroll
        for (int mf = 0; mf < 2; mf++) {
            int rl = w * 32 + mf * 16 + r;
            #pragma unroll
            for (int nf = 0; nf < 8; nf++) {
                *(float2*)(As + rl * 68 + nf * 8 + cq * 2) = make_float2(
                    __uint_as_float(f2tf(fmaxf(acc[mf][nf][0], 0.f))),
                    __uint_as_float(f2tf(fmaxf(acc[mf][nf][1], 0.f))));
                *(float2*)(As + (rl + 8) * 68 + nf * 8 + cq * 2) = make_float2(
                    __uint_as_float(f2tf(fmaxf(acc[mf][nf][2], 0.f))),
                    __uint_as_float(f2tf(fmaxf(acc[mf][nf][3], 0.f))));
            }
        }
        __syncthreads();
    };

    float acc[2][8][4];
    gemm64(Bt, bt, acc);
    relu_store(acc);
    gemm64(B1, bd1, acc);
    relu_store(acc);

    {
        float a2[2][4][4];
        #pragma unroll
        for (int nf = 0; nf < 4; nf++) {
            float blo = __ldg(bd2 + nf * 8 + cq * 2);
            float bhi = __ldg(bd2 + nf * 8 + cq * 2 + 1);
            #pragma unroll
            for (int mf = 0; mf < 2; mf++) {
                a2[mf][nf][0] = blo; a2[mf][nf][1] = bhi;
                a2[mf][nf][2] = blo; a2[mf][nf][3] = bhi;
            }
        }
        const float* Ab = As + w * 32 * 68;
        #pragma unroll
        for (int ks = 0; ks < 8; ks++) {
            uint32_t a[2][4];
            #pragma unroll
            for (int mf = 0; mf < 2; mf++) {
                const float* ap = Ab + (mf * 16 + r) * 68 + ks * 8 + cq;
                a[mf][0] = __float_as_uint(ap[0]);
                a[mf][1] = __float_as_uint(ap[8 * 68]);
                a[mf][2] = __float_as_uint(ap[4]);
                a[mf][3] = __float_as_uint(ap[8 * 68 + 4]);
            }
            #pragma unroll
            for (int nf = 0; nf < 4; nf++) {
                uint2 bv = *(const uint2*)(B2 + (ks * 4 + nf) * 64 + lane * 2);
                uint32_t b[2] = {bv.x, bv.y};
                mma_tf32(a2[0][nf], a[0], b);
                mma_tf32(a2[1][nf], a[1], b);
            }
        }
        #pragma unroll
        for (int mf = 0; mf < 2; mf++) {
            int rl = w * 32 + mf * 16 + r;
            int m = s_m[rl];
            if (m >= 0) {
                #pragma unroll
                for (int nf = 0; nf < 4; nf++) {
                    float2 u = *(const float2*)(xup + (size_t)m * 32 + nf * 8 + cq * 2);
                    *(float2*)(out + (size_t)m * 32 + nf * 8 + cq * 2) =
                        make_float2(a2[mf][nf][0] + u.x, a2[mf][nf][1] + u.y);
                }
            }
            int m2 = s_m[rl + 8];
            if (m2 >= 0) {
                #pragma unroll
                for (int nf = 0; nf < 4; nf++) {
                    float2 u = *(const float2*)(xup + (size_t)m2 * 32 + nf * 8 + cq * 2);
                    *(float2*)(out + (size_t)m2 * 32 + nf * 8 + cq * 2) =
                        make_float2(a2[mf][nf][2] + u.x, a2[mf][nf][3] + u.y);
                }
            }
        }
    }
}

// ---------------- launch -------------------------------------------------
extern "C" void kernel_launch(void* const* d_in, const int* in_sizes, int n_in,
                              void* d_out, int out_size)
{
    const float* feats  = (const float*)d_in[0];
    const float* xup    = (const float*)d_in[1];
    const int*   nbr    = (const int*)  d_in[2];
    const int*   parent = (const int*)  d_in[3];
    const int*   off    = (const int*)  d_in[4];
    const float* W1  = (const float*)d_in[5];
    const float* b1  = (const float*)d_in[6];
    const float* W2  = (const float*)d_in[7];
    const float* b2  = (const float*)d_in[8];
    const float* W3  = (const float*)d_in[9];
    const float* b3  = (const float*)d_in[10];
    const float* Wt  = (const float*)d_in[11];
    const float* bt  = (const float*)d_in[12];
    const float* Wd1 = (const float*)d_in[13];
    const float* bd1 = (const float*)d_in[14];
    const float* Wd2 = (const float*)d_in[15];
    const float* bd2 = (const float*)d_in[16];
    float* out = (float*)d_out;

    __half *finh, *ha, *hb;
    float *h1f;
    uint32_t *b1h, *b2h, *b3h;
    cudaGetSymbolAddress((void**)&finh, g_finh);
    cudaGetSymbolAddress((void**)&ha,   g_ha);
    cudaGetSymbolAddress((void**)&hb,   g_hb);
    cudaGetSymbolAddress((void**)&h1f,  g_h1);
    cudaGetSymbolAddress((void**)&b1h,  g_B1h);
    cudaGetSymbolAddress((void**)&b2h,  g_B2h);
    cudaGetSymbolAddress((void**)&b3h,  g_B3h);

    const int SMEM32 = 2 * 128 * 40 * 2 + 2 * 1024 * 4;   // 20480 + 8192 = 28672
    const int SMEM64 = 2 * 128 * 72 * 2 + 2 * 2048 * 4;   // 36864 + 16384 = 53248
    const int SMEMF  = (8704 + 4096 + 4096 + 2048) * 4 + 128 * 4; // 76288

    cudaFuncSetAttribute(conv3_h<32, true>,  cudaFuncAttributeMaxDynamicSharedMemorySize, SMEM32);
    cudaFuncSetAttribute(conv3_h<64, true>,  cudaFuncAttributeMaxDynamicSharedMemorySize, SMEM64);
    cudaFuncSetAttribute(conv3_h<64, false>, cudaFuncAttributeMaxDynamicSharedMemorySize, SMEM64);
    cudaFuncSetAttribute(tconv_dec_mma, cudaFuncAttributeMaxDynamicSharedMemorySize, SMEMF);

    prep_all<<<(C_TOT + 255) / 256, 256>>>(feats, W1, W2, W3, Wt, Wd1, Wd2);
    grp_build_kernel<<<(M_F + 255) / 256, 256>>>(off);
    grp_tiles_kernel<<<1, 32>>>();

    const int conv_grid = (N_C + 127) / 128;   // 782
    conv3_h<32, true><<<conv_grid, 128, SMEM32>>>(finh, nbr, b1h, b1, ha, nullptr);
    conv3_h<64, true><<<conv_grid, 128, SMEM64>>>(ha,   nbr, b2h, b2, hb, nullptr);
    conv3_h<64, false><<<conv_grid, 128, SMEM64>>>(hb,  nbr, b3h, b3, nullptr, h1f);

    const int max_tiles = (M_F + 127) / 128 + 7;   // 3132
    tconv_dec_mma<<<max_tiles, 128, SMEMF>>>(bt, bd1, bd2, parent, xup, out);
}